// round 10
// baseline (speedup 1.0000x reference)
#include <cuda_runtime.h>

#define GRID_H 13
#define GRID_W 13
#define NBOX   5
#define NELEM  85
#define NT     50
#define NTPAD  56
#define CPB    845            // cells per batch
#define NBATCH 256

#define NWARPS 8              // 256-thread blocks
#define CPW    4              // cells per warp (one per 8-lane group)
#define CELLS_PER_BLOCK (NWARPS * CPW)   // 32
#define NBLK_X 27
#define TOTAL_BLOCKS (NBLK_X * NBATCH)
#define TOTAL_FLOATS (NBATCH * CPB * NELEM)      // 18,387,200
#define MAX_CHUNK (TOTAL_FLOATS / 4 - 1)

#define FULL 0xFFFFFFFFu

__constant__ float c_anchors[10] = {
    0.57273f, 0.677385f, 1.87446f, 2.06253f, 3.33843f,
    5.47434f, 7.88282f, 3.52778f, 9.77052f, 9.16828f
};

// 5 accumulators on distinct L2 lines: 0 nb_coord, 1 nb_conf, 2 s_xywh, 3 s_conf, 4 s_class
__device__ float    g_acc[5 * 32];
__device__ unsigned g_done;

__device__ __forceinline__ float fast_sigmoid(float x) {
    return __fdividef(1.0f, 1.0f + __expf(-x));
}

__global__ __launch_bounds__(32 * NWARPS)
void yolo_loss_kernel(const float* __restrict__ y_true,
                      const float* __restrict__ y_pred,
                      const float* __restrict__ true_boxes,
                      float* __restrict__ out) {
    const int b    = blockIdx.y;
    const int warp = threadIdx.x >> 5;
    const int lane = threadIdx.x & 31;
    const int g    = lane >> 3;          // group = cell within warp
    const int s    = lane & 7;           // sublane within group

    // ---- shared (tiny): true-box tables + per-group box-scalar chunks ----
    __shared__ float4 s_ext[NTPAD];
    __shared__ float  s_b375[NTPAD];
    __shared__ float4 s_boxp[NWARPS][CPW][2];
    __shared__ float4 s_boxt[NWARPS][CPW][2];
    __shared__ float  s_part[NWARPS][6];

    if (threadIdx.x < NTPAD) {
        const int t = threadIdx.x;
        float4 v = (t < NT) ? ((const float4*)(true_boxes + b * NT * 4))[t]
                            : make_float4(1e9f, 0.f, 0.f, 0.f);
        s_ext[t]  = make_float4(v.x - v.z * 0.5f, v.x + v.z * 0.5f,
                                v.y - v.w * 0.5f, v.y + v.w * 0.5f);
        s_b375[t] = (t < NT) ? 0.375f * v.z * v.w : 3e38f;
    }
    __syncthreads();

    // ---- own-cell assignment (group g owns cell g) ----
    const int cellbase = blockIdx.x * CELLS_PER_BLOCK + warp * CPW;
    int cell_own = cellbase + g;
    const bool validc = (cell_own < CPB);
    if (!validc) cell_own = CPB - 1;

    const unsigned B  = (unsigned)(b * CPB + cell_own) * NELEM;  // cell float base
    const unsigned D  = B >> 2;                                  // aligned chunk base
    const int      a2 = (int)(B & 3u);                           // misalignment 0..3

    // ---- direct group-owned aligned float4 loads: chunks D + s + 8r (r=0..2) ----
    float4 cp[3], ct[3];
    #pragma unroll
    for (int r = 0; r < 3; r++) {
        unsigned c = D + (unsigned)(s + 8 * r);
        if (c > (unsigned)MAX_CHUNK) c = (unsigned)MAX_CHUNK;
        cp[r] = ((const float4*)y_pred)[c];
        ct[r] = ((const float4*)y_true)[c];
    }

    // ---- stage the two chunks holding box scalars (elements 0..4 live in q=0,1) ----
    if (s < 2) {
        s_boxp[warp][g][s] = cp[0];
        s_boxt[warp][g][s] = ct[0];
    }
    __syncwarp();

    // ---- per-lane LSE + argmax over classes, straight from registers ----
    // element e = 4*(s+8r) + j - a2 ; class c = e - 5 ; valid iff 0 <= c < 80
    // mask-free middle: q = s+8r in [2,20]; edges: q=1 (j>a2), q=21 (j<=a2); q=0,22,23 invalid
    float se = 0.0f;
    float av = -1.0f;
    int   ac = 1 << 20;
    const int cbase = 4 * s - a2 - 5;

    { // r = 0 : q = s
        const float pv[4] = {cp[0].x, cp[0].y, cp[0].z, cp[0].w};
        const float tv[4] = {ct[0].x, ct[0].y, ct[0].z, ct[0].w};
        #pragma unroll
        for (int j = 0; j < 4; j++) {
            const bool ok = (s >= 2) || (s == 1 && j > a2);
            se += __expf(ok ? pv[j] : -1e30f);
            if (ok && tv[j] > av) { av = tv[j]; ac = cbase + j; }
        }
    }
    { // r = 1 : q = s+8 in [8,15] — always fully valid
        const float pv[4] = {cp[1].x, cp[1].y, cp[1].z, cp[1].w};
        const float tv[4] = {ct[1].x, ct[1].y, ct[1].z, ct[1].w};
        #pragma unroll
        for (int j = 0; j < 4; j++) {
            se += __expf(pv[j]);
            if (tv[j] > av) { av = tv[j]; ac = cbase + 32 + j; }
        }
    }
    { // r = 2 : q = s+16 ; q<=20 full, q=21 partial, q>=22 invalid
        const float pv[4] = {cp[2].x, cp[2].y, cp[2].z, cp[2].w};
        const float tv[4] = {ct[2].x, ct[2].y, ct[2].z, ct[2].w};
        #pragma unroll
        for (int j = 0; j < 4; j++) {
            const bool ok = (s <= 4) || (s == 5 && j <= a2);
            se += __expf(ok ? pv[j] : -1e30f);
            if (ok && tv[j] > av) { av = tv[j]; ac = cbase + 64 + j; }
        }
    }

    // intra-group butterflies (first-max preserved via min class index on ties)
    #pragma unroll
    for (int o = 1; o < 8; o <<= 1) se += __shfl_xor_sync(FULL, se, o);
    #pragma unroll
    for (int o = 1; o < 8; o <<= 1) {
        const float v2 = __shfl_xor_sync(FULL, av, o);
        const int   c2 = __shfl_xor_sync(FULL, ac, o);
        if (v2 > av || (v2 == av && c2 < ac)) { av = v2; ac = c2; }
    }

    // ---- box scalars via conflict-free broadcast LDS (element e at flat pos a2+e) ----
    const float* bp = (const float*)&s_boxp[warp][g][0];
    const float* bt = (const float*)&s_boxt[warp][g][0];
    const float p0 = bp[a2 + 0], p1 = bp[a2 + 1], p2 = bp[a2 + 2],
                p3 = bp[a2 + 3], p4 = bp[a2 + 4];
    const float txo = bt[a2 + 0], tyo = bt[a2 + 1];
    const float two = bt[a2 + 2], tho = bt[a2 + 3];
    const float tco = bt[a2 + 4];

    // ---- predicted box (redundant within group) ----
    const int boxo = cell_own % NBOX;
    const int wo   = (cell_own / NBOX) % GRID_W;
    const int ho   = cell_own / (NBOX * GRID_W);
    const float px = fast_sigmoid(p0) + (float)wo;
    const float py = fast_sigmoid(p1) + (float)ho;
    const float pw = __expf(p2) * c_anchors[2 * boxo];
    const float ph = __expf(p3) * c_anchors[2 * boxo + 1];
    const float pc = fast_sigmoid(p4);
    const float pxmin = px - pw * 0.5f, pxmax = px + pw * 0.5f;
    const float pymin = py - ph * 0.5f, pymax = py + ph * 0.5f;
    const float parea = pw * ph;
    const float p375  = 0.375f * parea;

    // ---- divisionless best-IoU >= 0.6 test: 7 boxes per sublane ----
    bool hit = false;
    #pragma unroll
    for (int j = 0; j < 7; j++) {
        const int t = s + 8 * j;
        const float4 e = s_ext[t];
        const float iw = fmaxf(fminf(pxmax, e.y) - fmaxf(pxmin, e.x), 0.0f);
        const float ih = fmaxf(fminf(pymax, e.w) - fmaxf(pymin, e.z), 0.0f);
        hit = hit || (iw * ih >= p375 + s_b375[t]);
    }
    const unsigned bal  = __ballot_sync(FULL, hit);
    const bool     hitg = ((bal >> (g * 8)) & 0xFFu) != 0u;

    // ---- epilogue ----
    const float lt = y_pred[B + 5 + (unsigned)ac];   // broadcast LDG, L1-hit
    const float ce = __logf(se) - lt;

    const float iw = fmaxf(fminf(pxmax, txo + two * 0.5f) - fmaxf(pxmin, txo - two * 0.5f), 0.0f);
    const float ih = fmaxf(fminf(pymax, tyo + tho * 0.5f) - fmaxf(pymin, tyo - tho * 0.5f), 0.0f);
    const float ia = iw * ih;
    const float iou = __fdividef(ia, parea + two * tho - ia);

    const float cm = tco;                        // coord mask == class mask
    const float tc = iou * tco;
    const float fm = (hitg ? 0.0f : 1.0f) * (1.0f - tco) + 5.0f * tc;

    const bool use = (validc && s == 0);
    float acc0 = (use && cm > 0.0f) ? 1.0f : 0.0f;                       // nb_coord == nb_class
    float acc1 = (use && fm > 0.0f) ? 1.0f : 0.0f;                       // nb_conf
    float acc2 = use ? ((txo - px) * (txo - px) + (tyo - py) * (tyo - py)
                      + (two - pw) * (two - pw) + (tho - ph) * (tho - ph)) * cm : 0.0f;
    float acc3 = use ? (tc - pc) * (tc - pc) * fm : 0.0f;                // s_conf
    float acc4 = use ? ce * cm : 0.0f;                                   // s_class

    // ---- reduce group leaders -> lane 0 ----
    #pragma unroll
    for (int o = 8; o < 32; o <<= 1) {
        acc0 += __shfl_xor_sync(FULL, acc0, o);
        acc1 += __shfl_xor_sync(FULL, acc1, o);
        acc2 += __shfl_xor_sync(FULL, acc2, o);
        acc3 += __shfl_xor_sync(FULL, acc3, o);
        acc4 += __shfl_xor_sync(FULL, acc4, o);
    }

    if (lane == 0) {
        s_part[warp][0] = acc0; s_part[warp][1] = acc1; s_part[warp][2] = acc2;
        s_part[warp][3] = acc3; s_part[warp][4] = acc4;
    }
    __syncthreads();
    if (warp == 0) {
        #pragma unroll
        for (int i = 0; i < 5; i++) {
            float t = (lane < NWARPS) ? s_part[lane][i] : 0.0f;
            #pragma unroll
            for (int o = 4; o > 0; o >>= 1) t += __shfl_down_sync(FULL, t, o);
            if (lane == 0) atomicAdd(&g_acc[i * 32], t);
        }
    }

    // ---- last-block finalize (single launch) ----
    if (threadIdx.x == 0) {
        __threadfence();
        const unsigned t = atomicAdd(&g_done, 1u);
        if (t == (unsigned)(TOTAL_BLOCKS - 1)) {
            __threadfence();
            float a[5];
            #pragma unroll
            for (int i = 0; i < 5; i++) a[i] = atomicAdd(&g_acc[i * 32], 0.0f);
            const float nbc = a[0] + 1e-6f;
            const float nbf = a[1] + 1e-6f;
            out[0] = a[2] / nbc * 0.5f          // loss_xy + loss_wh
                   + a[3] / nbf * 0.5f          // loss_conf
                   + a[4] / nbc;                // loss_class (nb_class == nb_coord)
            #pragma unroll
            for (int i = 0; i < 5; i++) g_acc[i * 32] = 0.0f;
            g_done = 0u;
        }
    }
}

extern "C" void kernel_launch(void* const* d_in, const int* in_sizes, int n_in,
                              void* d_out, int out_size) {
    const float* y_true     = (const float*)d_in[0];
    const float* y_pred     = (const float*)d_in[1];
    const float* true_boxes = (const float*)d_in[2];
    float* out = (float*)d_out;

    dim3 grid(NBLK_X, NBATCH);
    yolo_loss_kernel<<<grid, 32 * NWARPS>>>(y_true, y_pred, true_boxes, out);
}

// round 11
// speedup vs baseline: 1.0149x; 1.0149x over previous
#include <cuda_runtime.h>

#define GRID_H 13
#define GRID_W 13
#define NBOX   5
#define NELEM  85
#define NT     50
#define NTPAD  56
#define CPB    845                      // cells per batch
#define NBATCH 256

#define NWARPS 8                        // 256-thread blocks
#define BLOCK_CELLS 32
#define CSTRIDE 88                      // conflict-free cell stride (88%32=24)
#define TOTAL_CELLS (NBATCH * CPB)      // 216320 = 6760 * 32 exactly
#define NBLOCKS (TOTAL_CELLS / BLOCK_CELLS)      // 6760
#define SPAN_CHUNKS (BLOCK_CELLS * NELEM / 4)    // 680 exactly

#define FULL 0xFFFFFFFFu

__constant__ float c_anchors[10] = {
    0.57273f, 0.677385f, 1.87446f, 2.06253f, 3.33843f,
    5.47434f, 7.88282f, 3.52778f, 9.77052f, 9.16828f
};

// 5 accumulators on distinct L2 lines: 0 nb_coord, 1 nb_conf, 2 s_xywh, 3 s_conf, 4 s_class
__device__ float    g_acc[5 * 32];
__device__ unsigned g_done;

__device__ __forceinline__ float fast_sigmoid(float x) {
    return __fdividef(1.0f, 1.0f + __expf(-x));
}

__global__ __launch_bounds__(32 * NWARPS)
void yolo_loss_kernel(const float* __restrict__ y_true,
                      const float* __restrict__ y_pred,
                      const float* __restrict__ true_boxes,
                      float* __restrict__ out) {
    const int tid  = threadIdx.x;
    const int warp = tid >> 5;
    const int lane = tid & 31;
    const int g    = lane >> 3;          // group = cell within warp's 4
    const int s    = lane & 7;           // sublane within group

    // ---- shared ----
    __shared__ float  s_p[BLOCK_CELLS * CSTRIDE];   // staged y_pred, per-cell stride 88
    __shared__ float  s_t[BLOCK_CELLS * CSTRIDE];   // staged y_true
    __shared__ float4 s_ext[2 * NTPAD];             // box extents for up to 2 batches
    __shared__ float  s_b375[2 * NTPAD];
    __shared__ float  s_part[NWARPS][6];

    const int gcell0 = blockIdx.x * BLOCK_CELLS;    // first global cell of block
    const int b0 = gcell0 / CPB;
    const int b1 = (gcell0 + BLOCK_CELLS - 1) / CPB;

    // ---- true-box tables for both possibly-touched batches ----
    if (tid < 2 * NTPAD) {
        const int half = tid / NTPAD;          // 0 -> b0, 1 -> b1
        const int t    = tid - half * NTPAD;
        const int bb   = half ? b1 : b0;
        float4 v = (t < NT) ? ((const float4*)(true_boxes + bb * NT * 4))[t]
                            : make_float4(1e9f, 0.f, 0.f, 0.f);
        s_ext[tid]  = make_float4(v.x - v.z * 0.5f, v.x + v.z * 0.5f,
                                  v.y - v.w * 0.5f, v.y + v.w * 0.5f);
        s_b375[tid] = (t < NT) ? 0.375f * v.z * v.w : 3e38f;
    }

    // ---- perfectly aligned block-span loads: 680 float4 chunks per tensor ----
    {
        const unsigned chunk0 = (unsigned)blockIdx.x * SPAN_CHUNKS;   // exact, aligned
        const float4* yp4 = (const float4*)y_pred;
        const float4* yt4 = (const float4*)y_true;
        #pragma unroll
        for (int r = 0; r < 3; r++) {
            const int m = tid + 256 * r;
            if (m < SPAN_CHUNKS) {
                const float4 vp = yp4[chunk0 + m];
                const float4 vt = yt4[chunk0 + m];
                const int p = 4 * m;                 // float offset in span
                int c = p / NELEM;                   // cell within block
                int e = p - c * NELEM;               // element within cell
                const float pv[4] = {vp.x, vp.y, vp.z, vp.w};
                const float tv[4] = {vt.x, vt.y, vt.z, vt.w};
                #pragma unroll
                for (int j = 0; j < 4; j++) {
                    s_p[c * CSTRIDE + e] = pv[j];
                    s_t[c * CSTRIDE + e] = tv[j];
                    if (++e == NELEM) { e = 0; c++; }
                }
            }
        }
    }
    __syncthreads();

    // ---- own-cell assignment (group g owns block-cell warp*4+g) ----
    const int cidx  = warp * 4 + g;                  // cell within block
    const int gcell = gcell0 + cidx;                 // global cell, always valid
    const int bown  = gcell / CPB;
    const int cell  = gcell - bown * CPB;            // cell within batch
    const int tb    = (bown == b0) ? 0 : NTPAD;      // table base
    const int gb    = cidx * CSTRIDE;

    // ---- box scalars (broadcast LDS; group bases on disjoint banks 0/24/16/8) ----
    const float p0 = s_p[gb + 0], p1 = s_p[gb + 1], p2 = s_p[gb + 2],
                p3 = s_p[gb + 3], p4 = s_p[gb + 4];
    const float txo = s_t[gb + 0], tyo = s_t[gb + 1];
    const float two = s_t[gb + 2], tho = s_t[gb + 3];
    const float tco = s_t[gb + 4];

    // ---- classes: e = 5 + s + 8i covers exactly [5,85), conflict-free LDS ----
    float se = 0.0f;
    float av = -1.0f; int ai = 0x7FFFFFFF;
    #pragma unroll
    for (int i = 0; i < 10; i++) {
        const int e = 5 + s + 8 * i;
        se += __expf(s_p[gb + e]);
        const float tte = s_t[gb + e];
        if (tte > av) { av = tte; ai = e; }
    }
    // intra-group butterflies (3 steps each; first-max via min index on ties)
    #pragma unroll
    for (int o = 1; o < 8; o <<= 1) se += __shfl_xor_sync(FULL, se, o);
    #pragma unroll
    for (int o = 1; o < 8; o <<= 1) {
        const float v2 = __shfl_xor_sync(FULL, av, o);
        const int   i2 = __shfl_xor_sync(FULL, ai, o);
        if (v2 > av || (v2 == av && i2 < ai)) { av = v2; ai = i2; }
    }

    // ---- predicted box (redundant within group: free in warp issue) ----
    const int boxo = cell % NBOX;
    const int wo   = (cell / NBOX) % GRID_W;
    const int ho   = cell / (NBOX * GRID_W);
    const float px = fast_sigmoid(p0) + (float)wo;
    const float py = fast_sigmoid(p1) + (float)ho;
    const float pw = __expf(p2) * c_anchors[2 * boxo];
    const float ph = __expf(p3) * c_anchors[2 * boxo + 1];
    const float pc = fast_sigmoid(p4);
    const float pxmin = px - pw * 0.5f, pxmax = px + pw * 0.5f;
    const float pymin = py - ph * 0.5f, pymax = py + ph * 0.5f;
    const float parea = pw * ph;
    const float p375  = 0.375f * parea;

    // ---- divisionless best-IoU >= 0.6 test: 7 boxes per sublane ----
    bool hit = false;
    #pragma unroll
    for (int j = 0; j < 7; j++) {
        const int t = tb + s + 8 * j;
        const float4 e = s_ext[t];
        const float iw = fmaxf(fminf(pxmax, e.y) - fmaxf(pxmin, e.x), 0.0f);
        const float ih = fmaxf(fminf(pymax, e.w) - fmaxf(pymin, e.z), 0.0f);
        hit = hit || (iw * ih >= p375 + s_b375[t]);
    }
    const unsigned bal  = __ballot_sync(FULL, hit);
    const bool     hitg = ((bal >> (g * 8)) & 0xFFu) != 0u;

    // ---- epilogue ----
    const float lt = s_p[gb + ai];               // LDS broadcast (ai uniform in group)
    const float ce = __logf(se) - lt;

    const float iw = fmaxf(fminf(pxmax, txo + two * 0.5f) - fmaxf(pxmin, txo - two * 0.5f), 0.0f);
    const float ih = fmaxf(fminf(pymax, tyo + tho * 0.5f) - fmaxf(pymin, tyo - tho * 0.5f), 0.0f);
    const float ia = iw * ih;
    const float iou = __fdividef(ia, parea + two * tho - ia);

    const float cm = tco;                        // coord mask == class mask
    const float tc = iou * tco;
    const float fm = (hitg ? 0.0f : 1.0f) * (1.0f - tco) + 5.0f * tc;

    const bool use = (s == 0);
    float acc0 = (use && cm > 0.0f) ? 1.0f : 0.0f;                       // nb_coord == nb_class
    float acc1 = (use && fm > 0.0f) ? 1.0f : 0.0f;                       // nb_conf
    float acc2 = use ? ((txo - px) * (txo - px) + (tyo - py) * (tyo - py)
                      + (two - pw) * (two - pw) + (tho - ph) * (tho - ph)) * cm : 0.0f;
    float acc3 = use ? (tc - pc) * (tc - pc) * fm : 0.0f;                // s_conf
    float acc4 = use ? ce * cm : 0.0f;                                   // s_class

    // ---- reduce group leaders -> lane 0 ----
    #pragma unroll
    for (int o = 8; o < 32; o <<= 1) {
        acc0 += __shfl_xor_sync(FULL, acc0, o);
        acc1 += __shfl_xor_sync(FULL, acc1, o);
        acc2 += __shfl_xor_sync(FULL, acc2, o);
        acc3 += __shfl_xor_sync(FULL, acc3, o);
        acc4 += __shfl_xor_sync(FULL, acc4, o);
    }

    if (lane == 0) {
        s_part[warp][0] = acc0; s_part[warp][1] = acc1; s_part[warp][2] = acc2;
        s_part[warp][3] = acc3; s_part[warp][4] = acc4;
    }
    __syncthreads();
    if (warp == 0) {
        #pragma unroll
        for (int i = 0; i < 5; i++) {
            float t = (lane < NWARPS) ? s_part[lane][i] : 0.0f;
            #pragma unroll
            for (int o = 4; o > 0; o >>= 1) t += __shfl_down_sync(FULL, t, o);
            if (lane == 0) atomicAdd(&g_acc[i * 32], t);
        }
    }

    // ---- last-block finalize (single launch) ----
    if (tid == 0) {
        __threadfence();
        const unsigned t = atomicAdd(&g_done, 1u);
        if (t == (unsigned)(NBLOCKS - 1)) {
            __threadfence();
            float a[5];
            #pragma unroll
            for (int i = 0; i < 5; i++) a[i] = atomicAdd(&g_acc[i * 32], 0.0f);
            const float nbc = a[0] + 1e-6f;
            const float nbf = a[1] + 1e-6f;
            out[0] = a[2] / nbc * 0.5f          // loss_xy + loss_wh
                   + a[3] / nbf * 0.5f          // loss_conf
                   + a[4] / nbc;                // loss_class (nb_class == nb_coord)
            #pragma unroll
            for (int i = 0; i < 5; i++) g_acc[i * 32] = 0.0f;
            g_done = 0u;
        }
    }
}

extern "C" void kernel_launch(void* const* d_in, const int* in_sizes, int n_in,
                              void* d_out, int out_size) {
    const float* y_true     = (const float*)d_in[0];
    const float* y_pred     = (const float*)d_in[1];
    const float* true_boxes = (const float*)d_in[2];
    float* out = (float*)d_out;

    yolo_loss_kernel<<<NBLOCKS, 32 * NWARPS>>>(y_true, y_pred, true_boxes, out);
}

// round 12
// speedup vs baseline: 1.1543x; 1.1373x over previous
#include <cuda_runtime.h>
#include <cstdint>

#define GRID_H 13
#define GRID_W 13
#define NBOX   5
#define NELEM  85
#define NT     50
#define NTPAD  56
#define CPB    845                      // cells per batch
#define NBATCH 256

#define NWARPS 8                        // 256-thread blocks
#define BLOCK_CELLS 32
#define TOTAL_CELLS (NBATCH * CPB)      // 216320 = 6760 * 32 exactly
#define NBLOCKS (TOTAL_CELLS / BLOCK_CELLS)      // 6760
#define SPAN_FLOATS (BLOCK_CELLS * NELEM)        // 2720
#define SPAN_BYTES  (SPAN_FLOATS * 4)            // 10880 (16B multiple)

#define FULL 0xFFFFFFFFu

__constant__ float c_anchors[10] = {
    0.57273f, 0.677385f, 1.87446f, 2.06253f, 3.33843f,
    5.47434f, 7.88282f, 3.52778f, 9.77052f, 9.16828f
};

// 5 accumulators on distinct L2 lines: 0 nb_coord, 1 nb_conf, 2 s_xywh, 3 s_conf, 4 s_class
__device__ float    g_acc[5 * 32];
__device__ unsigned g_done;

__device__ __forceinline__ float fast_sigmoid(float x) {
    return __fdividef(1.0f, 1.0f + __expf(-x));
}

__global__ __launch_bounds__(32 * NWARPS)
void yolo_loss_kernel(const float* __restrict__ y_true,
                      const float* __restrict__ y_pred,
                      const float* __restrict__ true_boxes,
                      float* __restrict__ out) {
    const int tid  = threadIdx.x;
    const int warp = tid >> 5;
    const int lane = tid & 31;
    const int g    = lane >> 3;          // group = cell within warp's 4
    const int s    = lane & 7;           // sublane within group

    // ---- shared ----
    __shared__ __align__(16) float s_p[SPAN_FLOATS];   // y_pred span (flat, stride 85)
    __shared__ __align__(16) float s_t[SPAN_FLOATS];   // y_true span
    __shared__ float4 s_ext[2 * NTPAD];                // box extents, up to 2 batches
    __shared__ float  s_b375[2 * NTPAD];
    __shared__ float  s_part[NWARPS][6];
    __shared__ __align__(8) unsigned long long s_mbar;

    const uint32_t mbar = (uint32_t)__cvta_generic_to_shared(&s_mbar);

    // ---- TMA bulk copy of both spans (single producer thread) ----
    if (tid == 0) {
        asm volatile("mbarrier.init.shared.b64 [%0], %1;" :: "r"(mbar), "r"(1) : "memory");
    }
    __syncthreads();
    if (tid == 0) {
        asm volatile("mbarrier.arrive.expect_tx.shared.b64 _, [%0], %1;"
                     :: "r"(mbar), "r"(2u * SPAN_BYTES) : "memory");
        const uint32_t dp = (uint32_t)__cvta_generic_to_shared(s_p);
        const uint32_t dt = (uint32_t)__cvta_generic_to_shared(s_t);
        const char* gp = (const char*)y_pred + (size_t)blockIdx.x * SPAN_BYTES;
        const char* gt = (const char*)y_true + (size_t)blockIdx.x * SPAN_BYTES;
        asm volatile("cp.async.bulk.shared::cta.global.mbarrier::complete_tx::bytes "
                     "[%0], [%1], %2, [%3];"
                     :: "r"(dp), "l"(gp), "r"((unsigned)SPAN_BYTES), "r"(mbar) : "memory");
        asm volatile("cp.async.bulk.shared::cta.global.mbarrier::complete_tx::bytes "
                     "[%0], [%1], %2, [%3];"
                     :: "r"(dt), "l"(gt), "r"((unsigned)SPAN_BYTES), "r"(mbar) : "memory");
    }

    // ---- true-box tables for both possibly-touched batches (overlaps with TMA) ----
    const int gcell0 = blockIdx.x * BLOCK_CELLS;
    const int b0 = gcell0 / CPB;
    const int b1 = (gcell0 + BLOCK_CELLS - 1) / CPB;
    if (tid < 2 * NTPAD) {
        const int half = tid / NTPAD;
        const int t    = tid - half * NTPAD;
        const int bb   = half ? b1 : b0;
        float4 v = (t < NT) ? ((const float4*)(true_boxes + bb * NT * 4))[t]
                            : make_float4(1e9f, 0.f, 0.f, 0.f);
        s_ext[tid]  = make_float4(v.x - v.z * 0.5f, v.x + v.z * 0.5f,
                                  v.y - v.w * 0.5f, v.y + v.w * 0.5f);
        s_b375[tid] = (t < NT) ? 0.375f * v.z * v.w : 3e38f;
    }
    __syncthreads();   // s_ext visible

    // ---- wait for TMA completion (acquire) ----
    {
        uint32_t done;
        asm volatile("{\n\t.reg .pred p;\n\t"
                     "mbarrier.try_wait.parity.acquire.cta.shared::cta.b64 p, [%1], %2;\n\t"
                     "selp.b32 %0, 1, 0, p;\n\t}"
                     : "=r"(done) : "r"(mbar), "r"(0u) : "memory");
        while (!done) {
            asm volatile("{\n\t.reg .pred p;\n\t"
                         "mbarrier.try_wait.parity.acquire.cta.shared::cta.b64 p, [%1], %2;\n\t"
                         "selp.b32 %0, 1, 0, p;\n\t}"
                         : "=r"(done) : "r"(mbar), "r"(0u) : "memory");
        }
    }

    // ---- own-cell assignment (group g owns block-cell warp*4+g) ----
    const int cidx  = warp * 4 + g;
    const int gcell = gcell0 + cidx;                 // always valid (exact tiling)
    const int bown  = gcell / CPB;
    const int cell  = gcell - bown * CPB;
    const int tb    = (bown == b0) ? 0 : NTPAD;
    const int gb    = cidx * NELEM;                  // flat stride 85

    // ---- box scalars (broadcast LDS; partial 2-way conflicts acceptable) ----
    const float p0 = s_p[gb + 0], p1 = s_p[gb + 1], p2 = s_p[gb + 2],
                p3 = s_p[gb + 3], p4 = s_p[gb + 4];
    const float txo = s_t[gb + 0], tyo = s_t[gb + 1];
    const float two = s_t[gb + 2], tho = s_t[gb + 3];
    const float tco = s_t[gb + 4];

    // ---- classes: e = 5 + s + 8i covers exactly [5,85) ----
    float se = 0.0f;
    float av = -1.0f; int ai = 0x7FFFFFFF;
    #pragma unroll
    for (int i = 0; i < 10; i++) {
        const int e = 5 + s + 8 * i;
        se += __expf(s_p[gb + e]);
        const float tte = s_t[gb + e];
        if (tte > av) { av = tte; ai = e; }
    }
    // intra-group butterflies (3 steps; first-max via min index on ties)
    #pragma unroll
    for (int o = 1; o < 8; o <<= 1) se += __shfl_xor_sync(FULL, se, o);
    #pragma unroll
    for (int o = 1; o < 8; o <<= 1) {
        const float v2 = __shfl_xor_sync(FULL, av, o);
        const int   i2 = __shfl_xor_sync(FULL, ai, o);
        if (v2 > av || (v2 == av && i2 < ai)) { av = v2; ai = i2; }
    }

    // ---- predicted box (redundant within group: free in warp issue) ----
    const int boxo = cell % NBOX;
    const int wo   = (cell / NBOX) % GRID_W;
    const int ho   = cell / (NBOX * GRID_W);
    const float px = fast_sigmoid(p0) + (float)wo;
    const float py = fast_sigmoid(p1) + (float)ho;
    const float pw = __expf(p2) * c_anchors[2 * boxo];
    const float ph = __expf(p3) * c_anchors[2 * boxo + 1];
    const float pc = fast_sigmoid(p4);
    const float pxmin = px - pw * 0.5f, pxmax = px + pw * 0.5f;
    const float pymin = py - ph * 0.5f, pymax = py + ph * 0.5f;
    const float parea = pw * ph;
    const float p375  = 0.375f * parea;

    // ---- divisionless best-IoU >= 0.6 test: 7 boxes per sublane ----
    bool hit = false;
    #pragma unroll
    for (int j = 0; j < 7; j++) {
        const int t = tb + s + 8 * j;
        const float4 e = s_ext[t];
        const float iw = fmaxf(fminf(pxmax, e.y) - fmaxf(pxmin, e.x), 0.0f);
        const float ih = fmaxf(fminf(pymax, e.w) - fmaxf(pymin, e.z), 0.0f);
        hit = hit || (iw * ih >= p375 + s_b375[t]);
    }
    const unsigned bal  = __ballot_sync(FULL, hit);
    const bool     hitg = ((bal >> (g * 8)) & 0xFFu) != 0u;

    // ---- epilogue ----
    const float lt = s_p[gb + ai];               // LDS broadcast (ai uniform in group)
    const float ce = __logf(se) - lt;

    const float iw = fmaxf(fminf(pxmax, txo + two * 0.5f) - fmaxf(pxmin, txo - two * 0.5f), 0.0f);
    const float ih = fmaxf(fminf(pymax, tyo + tho * 0.5f) - fmaxf(pymin, tyo - tho * 0.5f), 0.0f);
    const float ia = iw * ih;
    const float iou = __fdividef(ia, parea + two * tho - ia);

    const float cm = tco;                        // coord mask == class mask
    const float tc = iou * tco;
    const float fm = (hitg ? 0.0f : 1.0f) * (1.0f - tco) + 5.0f * tc;

    const bool use = (s == 0);
    float acc0 = (use && cm > 0.0f) ? 1.0f : 0.0f;                       // nb_coord == nb_class
    float acc1 = (use && fm > 0.0f) ? 1.0f : 0.0f;                       // nb_conf
    float acc2 = use ? ((txo - px) * (txo - px) + (tyo - py) * (tyo - py)
                      + (two - pw) * (two - pw) + (tho - ph) * (tho - ph)) * cm : 0.0f;
    float acc3 = use ? (tc - pc) * (tc - pc) * fm : 0.0f;                // s_conf
    float acc4 = use ? ce * cm : 0.0f;                                   // s_class

    // ---- reduce group leaders -> lane 0 ----
    #pragma unroll
    for (int o = 8; o < 32; o <<= 1) {
        acc0 += __shfl_xor_sync(FULL, acc0, o);
        acc1 += __shfl_xor_sync(FULL, acc1, o);
        acc2 += __shfl_xor_sync(FULL, acc2, o);
        acc3 += __shfl_xor_sync(FULL, acc3, o);
        acc4 += __shfl_xor_sync(FULL, acc4, o);
    }

    if (lane == 0) {
        s_part[warp][0] = acc0; s_part[warp][1] = acc1; s_part[warp][2] = acc2;
        s_part[warp][3] = acc3; s_part[warp][4] = acc4;
    }
    __syncthreads();
    if (warp == 0) {
        #pragma unroll
        for (int i = 0; i < 5; i++) {
            float t = (lane < NWARPS) ? s_part[lane][i] : 0.0f;
            #pragma unroll
            for (int o = 4; o > 0; o >>= 1) t += __shfl_down_sync(FULL, t, o);
            if (lane == 0) atomicAdd(&g_acc[i * 32], t);
        }
    }

    // ---- last-block finalize (single launch) ----
    if (tid == 0) {
        __threadfence();
        const unsigned t = atomicAdd(&g_done, 1u);
        if (t == (unsigned)(NBLOCKS - 1)) {
            __threadfence();
            float a[5];
            #pragma unroll
            for (int i = 0; i < 5; i++) a[i] = atomicAdd(&g_acc[i * 32], 0.0f);
            const float nbc = a[0] + 1e-6f;
            const float nbf = a[1] + 1e-6f;
            out[0] = a[2] / nbc * 0.5f          // loss_xy + loss_wh
                   + a[3] / nbf * 0.5f          // loss_conf
                   + a[4] / nbc;                // loss_class (nb_class == nb_coord)
            #pragma unroll
            for (int i = 0; i < 5; i++) g_acc[i * 32] = 0.0f;
            g_done = 0u;
        }
    }
}

extern "C" void kernel_launch(void* const* d_in, const int* in_sizes, int n_in,
                              void* d_out, int out_size) {
    const float* y_true     = (const float*)d_in[0];
    const float* y_pred     = (const float*)d_in[1];
    const float* true_boxes = (const float*)d_in[2];
    float* out = (float*)d_out;

    yolo_loss_kernel<<<NBLOCKS, 32 * NWARPS>>>(y_true, y_pred, true_boxes, out);
}